// round 13
// baseline (speedup 1.0000x reference)
#include <cuda_runtime.h>
#include <cuda_bf16.h>
#include <stdint.h>
#include <math.h>

#define L_STEPS 512
#define BATCH   128
#define HID     512
#define DIN     512

// ---------------- device scratch ----------------
__device__ __nv_bfloat16 g_h_hi[2][BATCH * HID];
__device__ __nv_bfloat16 g_h_lo[2][BATCH * HID];
__device__ unsigned g_bar_arrive = 0;
__device__ volatile unsigned g_bar_gen = 0;
__device__ unsigned g_garr[8 * 32];
__device__ unsigned g_ggen[8 * 32];

#define SCAN_BLOCKS  128
#define SCAN_THREADS 256

// smem layout (bytes), stride 520 bf16 per row everywhere
#define W_STRIDE 520
#define H_STRIDE 520
#define WS_B (32 * W_STRIDE * 2)     // 33280
#define HS_B (16 * H_STRIDE * 2)     // 16640
#define OFF_WHI  0                    // Wh hi   [32][520]
#define OFF_WLO  (WS_B)               // Wh lo
#define OFF_HHI  (2 * WS_B)           // h  hi   [16][520]
#define OFF_HLO  (2 * WS_B + HS_B)    // h  lo
#define OFF_XWHI (2 * WS_B + 2 * HS_B)            // Wx hi [32][520]
#define OFF_XWLO (3 * WS_B + 2 * HS_B)            // Wx lo
#define OFF_XHI  (4 * WS_B + 2 * HS_B)            // x  hi [16][520]
#define OFF_XLO  (4 * WS_B + 3 * HS_B)            // x  lo
#define OFF_XP   (4 * WS_B + 4 * HS_B)            // xp ring: 2 x 16 x 32 f32
#define SMEM_BYTES (4 * WS_B + 4 * HS_B + 4096)   // 203776

// ---------------- barriers ----------------
__device__ __forceinline__ void full_grid_barrier() {
    __threadfence();
    __syncthreads();
    if (threadIdx.x == 0) {
        unsigned gen = g_bar_gen;
        if (atomicAdd(&g_bar_arrive, 1u) == SCAN_BLOCKS - 1) {
            g_bar_arrive = 0;
            __threadfence();
            g_bar_gen = gen + 1;
        } else {
            while (g_bar_gen == gen) { __nanosleep(32); }
        }
    }
    __syncthreads();
}

// acq_rel group barrier: 16 CTAs of the same bt group (R6 — proven best)
__device__ __forceinline__ void group_barrier(int grp) {
    __syncthreads();
    if (threadIdx.x == 0) {
        unsigned* arr = &g_garr[grp * 32];
        unsigned* gen = &g_ggen[grp * 32];
        unsigned g;
        asm volatile("ld.relaxed.gpu.u32 %0, [%1];" : "=r"(g) : "l"(gen));
        unsigned old;
        asm volatile("atom.add.acq_rel.gpu.u32 %0, [%1], 1;" : "=r"(old) : "l"(arr));
        if (old == 15) {
            asm volatile("st.relaxed.gpu.u32 [%0], 0;" :: "l"(arr));
            unsigned ng = g + 1;
            asm volatile("st.release.gpu.u32 [%0], %1;" :: "l"(gen), "r"(ng));
        } else {
            unsigned cur;
            do {
                __nanosleep(20);
                asm volatile("ld.acquire.gpu.u32 %0, [%1];" : "=r"(cur) : "l"(gen));
            } while (cur == g);
        }
    }
    __syncthreads();
}

#define NB_ARRIVE(id) asm volatile("bar.arrive %0, 256;" :: "r"(id) : "memory")
#define NB_SYNC(id)   asm volatile("bar.sync %0, 256;"   :: "r"(id) : "memory")
#define NB_SYNC_HALF(id) asm volatile("bar.sync %0, 128;" :: "r"(id) : "memory")

// ---------------- mma / ldmatrix helpers ----------------
__device__ __forceinline__ void mma_bf16(float* c,
                                         uint32_t a0, uint32_t a1, uint32_t a2, uint32_t a3,
                                         uint32_t b0, uint32_t b1) {
    asm volatile(
        "mma.sync.aligned.m16n8k16.row.col.f32.bf16.bf16.f32 "
        "{%0,%1,%2,%3}, {%4,%5,%6,%7}, {%8,%9}, {%0,%1,%2,%3};"
        : "+f"(c[0]), "+f"(c[1]), "+f"(c[2]), "+f"(c[3])
        : "r"(a0), "r"(a1), "r"(a2), "r"(a3), "r"(b0), "r"(b1));
}
__device__ __forceinline__ void ldsm_x4(uint32_t r[4], uint32_t addr) {
    asm volatile("ldmatrix.sync.aligned.m8n8.x4.shared.b16 {%0,%1,%2,%3}, [%4];"
                 : "=r"(r[0]), "=r"(r[1]), "=r"(r[2]), "=r"(r[3]) : "r"(addr));
}
__device__ __forceinline__ void ldsm_x2(uint32_t r[2], uint32_t addr) {
    asm volatile("ldmatrix.sync.aligned.m8n8.x2.shared.b16 {%0,%1}, [%2];"
                 : "=r"(r[0]), "=r"(r[1]) : "r"(addr));
}
__device__ __forceinline__ void split_bf16(float v, __nv_bfloat16& hi, __nv_bfloat16& lo) {
    hi = __float2bfloat16(v);
    lo = __float2bfloat16(v - __bfloat162float(hi));
}
__device__ __forceinline__ float fast_tanh(float x) {
    float e = __expf(2.0f * x);
    return 1.0f - 2.0f / (e + 1.0f);
}

// ---------------- fused persistent kernel --------------------------------------
// 128 CTAs, groups of 16 by bt. Warps 0-3: scan MMA (R6 structure).
// Warps 4-7: stage h chunk1, then produce xp[t+1] (x[t+1] @ Wx^T + bias) into a
// 2-slot smem ring via 3-term bf16-split MMA. Consumers read xp from smem.
__global__ void __launch_bounds__(SCAN_THREADS, 1) rnn_fused_kernel(
    const float* __restrict__ x,  const float* __restrict__ h0,
    const float* __restrict__ Wx, const float* __restrict__ bx,
    const float* __restrict__ Wh, const float* __restrict__ bh,
    float* __restrict__ out)
{
    extern __shared__ char sm[];
    __nv_bfloat16* ws_hi = (__nv_bfloat16*)(sm + OFF_WHI);
    __nv_bfloat16* ws_lo = (__nv_bfloat16*)(sm + OFF_WLO);
    __nv_bfloat16* hs_hi = (__nv_bfloat16*)(sm + OFF_HHI);
    __nv_bfloat16* hs_lo = (__nv_bfloat16*)(sm + OFF_HLO);
    __nv_bfloat16* xw_hi = (__nv_bfloat16*)(sm + OFF_XWHI);
    __nv_bfloat16* xw_lo = (__nv_bfloat16*)(sm + OFF_XWLO);
    __nv_bfloat16* xs_hi = (__nv_bfloat16*)(sm + OFF_XHI);
    __nv_bfloat16* xs_lo = (__nv_bfloat16*)(sm + OFF_XLO);
    float*         xpring = (float*)(sm + OFF_XP);   // [2][16][32]

    const int tid  = threadIdx.x;
    const int lane = tid & 31;
    const int w    = tid >> 5;
    const int bt = blockIdx.x >> 4;
    const int ht = blockIdx.x & 15;
    const int b0 = bt << 4;
    const int j0 = ht << 5;

    // ---- init: split h0 into bf16 hi/lo (grid-strided) ----
    {
        int gtid = blockIdx.x * SCAN_THREADS + tid;
        #pragma unroll
        for (int r = 0; r < 2; ++r) {
            int i = gtid + r * (SCAN_BLOCKS * SCAN_THREADS);
            float v = __ldg(h0 + i);
            __nv_bfloat16 hi, lo;
            split_bf16(v, hi, lo);
            g_h_hi[0][i] = hi;
            g_h_lo[0][i] = lo;
        }
    }
    // ---- init: split Wh and Wx slices (rows j0..j0+31) into smem ----
    for (int i = tid; i < 32 * HID; i += SCAN_THREADS) {
        int n = i >> 9, k = i & 511;
        __nv_bfloat16 hi, lo;
        float v = __ldg(Wh + (size_t)(j0 + n) * HID + k);
        split_bf16(v, hi, lo);
        ws_hi[n * W_STRIDE + k] = hi;
        ws_lo[n * W_STRIDE + k] = lo;
        float u = __ldg(Wx + (size_t)(j0 + n) * HID + k);
        split_bf16(u, hi, lo);
        xw_hi[n * W_STRIDE + k] = hi;
        xw_lo[n * W_STRIDE + k] = lo;
    }
    __syncthreads();

    // ---- ldsm base addresses ----
    uint32_t hs_hi_u = (uint32_t)__cvta_generic_to_shared(hs_hi);
    uint32_t hs_lo_u = (uint32_t)__cvta_generic_to_shared(hs_lo);
    uint32_t ws_hi_u = (uint32_t)__cvta_generic_to_shared(ws_hi);
    uint32_t ws_lo_u = (uint32_t)__cvta_generic_to_shared(ws_lo);
    uint32_t xs_hi_u = (uint32_t)__cvta_generic_to_shared(xs_hi);
    uint32_t xs_lo_u = (uint32_t)__cvta_generic_to_shared(xs_lo);
    uint32_t xw_hi_u = (uint32_t)__cvta_generic_to_shared(xw_hi);
    uint32_t xw_lo_u = (uint32_t)__cvta_generic_to_shared(xw_lo);

    const int arow  = (lane & 7) + ((lane >> 3) & 1) * 8;
    const int akoff = (lane >> 4) * 16;
    const int wj    = w & 3;                        // column-warp index (0..3)
    const int brow  = 8 * wj + (lane & 7);
    const int bkoff = ((lane >> 3) & 1) * 16;

    // scan (w0-3): A from hs, B from ws
    const uint32_t aHiBase = hs_hi_u + arow * (H_STRIDE * 2) + akoff;
    const uint32_t aLoBase = hs_lo_u + arow * (H_STRIDE * 2) + akoff;
    const uint32_t bHiBase = ws_hi_u + brow * (W_STRIDE * 2) + bkoff;
    const uint32_t bLoBase = ws_lo_u + brow * (W_STRIDE * 2) + bkoff;
    // xproj (w4-7): A from xs, B from xw
    const uint32_t xaHiBase = xs_hi_u + arow * (H_STRIDE * 2) + akoff;
    const uint32_t xaLoBase = xs_lo_u + arow * (H_STRIDE * 2) + akoff;
    const uint32_t xbHiBase = xw_hi_u + brow * (W_STRIDE * 2) + bkoff;
    const uint32_t xbLoBase = xw_lo_u + brow * (W_STRIDE * 2) + bkoff;

    const int er = lane >> 2;
    const int ec = 2 * (lane & 3);
    const int jcol = j0 + 8 * wj + ec;
    const size_t o1 = (size_t)(b0 + er) * HID + jcol;
    const size_t o2 = (size_t)(b0 + er + 8) * HID + jcol;
    // ring offsets (floats): [slot*512 + row*32 + col]
    const int rc = 8 * wj + ec;

    // bias for this thread's two columns (producers add it into xp)
    const float bb0 = __ldg(bx + jcol) + __ldg(bh + jcol);
    const float bb1 = __ldg(bx + jcol + 1) + __ldg(bh + jcol + 1);

    const int local = tid - 128;   // for w4-7

    // ---- prologue: w4-7 produce xp[0] into ring slot 0 ----
    if (w >= 4) {
        // stage x[0] tile (rows b0..b0+15) split hi/lo
        const float4* s4 = (const float4*)(x + (size_t)b0 * HID);
        #pragma unroll
        for (int wave = 0; wave < 2; ++wave) {
            float4 v[8];
            #pragma unroll
            for (int n = 0; n < 8; ++n)
                v[n] = __ldg(s4 + local + (wave * 8 + n) * 128);
            #pragma unroll
            for (int n = 0; n < 8; ++n) {
                int i = local + (wave * 8 + n) * 128;
                int row = i >> 7, c4 = i & 127;
                __nv_bfloat16 h0b, l0b, h1b, l1b, h2b, l2b, h3b, l3b;
                split_bf16(v[n].x, h0b, l0b); split_bf16(v[n].y, h1b, l1b);
                split_bf16(v[n].z, h2b, l2b); split_bf16(v[n].w, h3b, l3b);
                __nv_bfloat162* pH = (__nv_bfloat162*)(xs_hi + row * H_STRIDE + (c4 << 2));
                __nv_bfloat162* pL = (__nv_bfloat162*)(xs_lo + row * H_STRIDE + (c4 << 2));
                pH[0] = __nv_bfloat162(h0b, h1b); pH[1] = __nv_bfloat162(h2b, h3b);
                pL[0] = __nv_bfloat162(l0b, l1b); pL[1] = __nv_bfloat162(l2b, l3b);
            }
        }
        NB_SYNC_HALF(2);
        float chh[4] = {0.f,0.f,0.f,0.f}, chl[4] = {0.f,0.f,0.f,0.f}, clh[4] = {0.f,0.f,0.f,0.f};
        #pragma unroll 8
        for (int ki = 0; ki < 32; ++ki) {
            const uint32_t koff = ki * 32;
            uint32_t ah[4], al[4], bh2[2], bl2[2];
            ldsm_x4(ah, xaHiBase + koff);
            ldsm_x4(al, xaLoBase + koff);
            ldsm_x2(bh2, xbHiBase + koff);
            ldsm_x2(bl2, xbLoBase + koff);
            mma_bf16(chh, ah[0], ah[1], ah[2], ah[3], bh2[0], bh2[1]);
            mma_bf16(chl, ah[0], ah[1], ah[2], ah[3], bl2[0], bl2[1]);
            mma_bf16(clh, al[0], al[1], al[2], al[3], bh2[0], bh2[1]);
        }
        float* ring0 = xpring;   // slot 0
        *(float2*)(ring0 + er * 32 + rc)       = make_float2(chh[0]+chl[0]+clh[0]+bb0,
                                                             chh[1]+chl[1]+clh[1]+bb1);
        *(float2*)(ring0 + (er + 8) * 32 + rc) = make_float2(chh[2]+chl[2]+clh[2]+bb0,
                                                             chh[3]+chl[3]+clh[3]+bb1);
    }
    full_grid_barrier();

    int p = 0;
    for (int t = 0; t < L_STEPS; ++t) {
        float* gout = out + (size_t)t * (BATCH * HID);
        const float4* srcH = (const float4*)(g_h_hi[p] + b0 * HID);
        const float4* srcL = (const float4*)(g_h_lo[p] + b0 * HID);
        float4* dH = (float4*)hs_hi;
        float4* dL = (float4*)hs_lo;

        // stage h chunk0 (bf16 cols 0..255): all warps
        #pragma unroll
        for (int n = 0; n < 2; ++n) {
            int i = tid + (n << 8);
            int row = i >> 5, c4 = i & 31;
            dH[row * 65 + c4] = __ldcg(srcH + row * 64 + c4);
            dL[row * 65 + c4] = __ldcg(srcL + row * 64 + c4);
        }
        __syncthreads();

        if (w < 4) {
            // xp from smem ring, slot t&1 (bias already included)
            const float* ring = xpring + (t & 1) * 512;
            float2 xp1 = *(const float2*)(ring + er * 32 + rc);
            float2 xp2 = *(const float2*)(ring + (er + 8) * 32 + rc);

            float chh[4] = {0.f,0.f,0.f,0.f}, chl[4] = {0.f,0.f,0.f,0.f}, clh[4] = {0.f,0.f,0.f,0.f};
            #pragma unroll 8
            for (int ki = 0; ki < 16; ++ki) {
                const uint32_t koff = ki * 32;
                uint32_t ah[4], al[4], bh2[2], bl2[2];
                ldsm_x4(ah, aHiBase + koff);
                ldsm_x4(al, aLoBase + koff);
                ldsm_x2(bh2, bHiBase + koff);
                ldsm_x2(bl2, bLoBase + koff);
                mma_bf16(chh, ah[0], ah[1], ah[2], ah[3], bh2[0], bh2[1]);
                mma_bf16(chl, ah[0], ah[1], ah[2], ah[3], bl2[0], bl2[1]);
                mma_bf16(clh, al[0], al[1], al[2], al[3], bh2[0], bh2[1]);
            }
            NB_SYNC(1);    // chunk1 staged
            #pragma unroll 8
            for (int ki = 16; ki < 32; ++ki) {
                const uint32_t koff = ki * 32;
                uint32_t ah[4], al[4], bh2[2], bl2[2];
                ldsm_x4(ah, aHiBase + koff);
                ldsm_x4(al, aLoBase + koff);
                ldsm_x2(bh2, bHiBase + koff);
                ldsm_x2(bl2, bLoBase + koff);
                mma_bf16(chh, ah[0], ah[1], ah[2], ah[3], bh2[0], bh2[1]);
                mma_bf16(chl, ah[0], ah[1], ah[2], ah[3], bl2[0], bl2[1]);
                mma_bf16(clh, al[0], al[1], al[2], al[3], bh2[0], bh2[1]);
            }

            float hn0 = fast_tanh(chh[0] + chl[0] + clh[0] + xp1.x);
            float hn1 = fast_tanh(chh[1] + chl[1] + clh[1] + xp1.y);
            float hn2 = fast_tanh(chh[2] + chl[2] + clh[2] + xp2.x);
            float hn3 = fast_tanh(chh[3] + chl[3] + clh[3] + xp2.y);

            __nv_bfloat16 h0b, l0b, h1b, l1b, h2b, l2b, h3b, l3b;
            split_bf16(hn0, h0b, l0b);
            split_bf16(hn1, h1b, l1b);
            split_bf16(hn2, h2b, l2b);
            split_bf16(hn3, h3b, l3b);

            // publish next-step state FIRST (inter-CTA critical path)
            __nv_bfloat16* ghh = g_h_hi[p ^ 1];
            __nv_bfloat16* ghl = g_h_lo[p ^ 1];
            *(__nv_bfloat162*)(ghh + o1) = __nv_bfloat162(h0b, h1b);
            *(__nv_bfloat162*)(ghh + o2) = __nv_bfloat162(h2b, h3b);
            *(__nv_bfloat162*)(ghl + o1) = __nv_bfloat162(l0b, l1b);
            *(__nv_bfloat162*)(ghl + o2) = __nv_bfloat162(l2b, l3b);

            // hAll fp32 stores
            *(float2*)(gout + o1) = make_float2(hn0, hn1);
            *(float2*)(gout + o2) = make_float2(hn2, hn3);

            if (t == L_STEPS - 1) {
                float* hlast = out + (size_t)L_STEPS * BATCH * HID;
                *(float2*)(hlast + o1) = make_float2(hn0, hn1);
                *(float2*)(hlast + o2) = make_float2(hn2, hn3);
            }
        } else {
            // stage h chunk1 (bf16 cols 256..511)
            #pragma unroll
            for (int n = 0; n < 4; ++n) {
                int i = local + (n << 7);
                int row = i >> 5, c4 = 32 + (i & 31);
                dH[row * 65 + c4] = __ldcg(srcH + row * 64 + c4);
                dL[row * 65 + c4] = __ldcg(srcL + row * 64 + c4);
            }
            NB_ARRIVE(1);

            if (t < L_STEPS - 1) {
                // stage x[t+1] tile, split hi/lo
                const float4* s4 = (const float4*)(x + ((size_t)(t + 1) * BATCH + b0) * HID);
                #pragma unroll
                for (int wave = 0; wave < 2; ++wave) {
                    float4 v[8];
                    #pragma unroll
                    for (int n = 0; n < 8; ++n)
                        v[n] = __ldg(s4 + local + (wave * 8 + n) * 128);
                    #pragma unroll
                    for (int n = 0; n < 8; ++n) {
                        int i = local + (wave * 8 + n) * 128;
                        int row = i >> 7, c4 = i & 127;
                        __nv_bfloat16 h0b, l0b, h1b, l1b, h2b, l2b, h3b, l3b;
                        split_bf16(v[n].x, h0b, l0b); split_bf16(v[n].y, h1b, l1b);
                        split_bf16(v[n].z, h2b, l2b); split_bf16(v[n].w, h3b, l3b);
                        __nv_bfloat162* pH = (__nv_bfloat162*)(xs_hi + row * H_STRIDE + (c4 << 2));
                        __nv_bfloat162* pL = (__nv_bfloat162*)(xs_lo + row * H_STRIDE + (c4 << 2));
                        pH[0] = __nv_bfloat162(h0b, h1b); pH[1] = __nv_bfloat162(h2b, h3b);
                        pL[0] = __nv_bfloat162(l0b, l1b); pL[1] = __nv_bfloat162(l2b, l3b);
                    }
                }
                NB_SYNC_HALF(2);

                float chh[4] = {0.f,0.f,0.f,0.f}, chl[4] = {0.f,0.f,0.f,0.f}, clh[4] = {0.f,0.f,0.f,0.f};
                #pragma unroll 8
                for (int ki = 0; ki < 32; ++ki) {
                    const uint32_t koff = ki * 32;
                    uint32_t ah[4], al[4], bh2[2], bl2[2];
                    ldsm_x4(ah, xaHiBase + koff);
                    ldsm_x4(al, xaLoBase + koff);
                    ldsm_x2(bh2, xbHiBase + koff);
                    ldsm_x2(bl2, xbLoBase + koff);
                    mma_bf16(chh, ah[0], ah[1], ah[2], ah[3], bh2[0], bh2[1]);
                    mma_bf16(chl, ah[0], ah[1], ah[2], ah[3], bl2[0], bl2[1]);
                    mma_bf16(clh, al[0], al[1], al[2], al[3], bh2[0], bh2[1]);
                }
                float* ring = xpring + ((t + 1) & 1) * 512;
                *(float2*)(ring + er * 32 + rc)       = make_float2(chh[0]+chl[0]+clh[0]+bb0,
                                                                    chh[1]+chl[1]+clh[1]+bb1);
                *(float2*)(ring + (er + 8) * 32 + rc) = make_float2(chh[2]+chl[2]+clh[2]+bb0,
                                                                    chh[3]+chl[3]+clh[3]+bb1);
            }
        }

        if (t != L_STEPS - 1) group_barrier(bt);
        p ^= 1;
    }
}

// ---------------- launch -------------------------------------------------------
extern "C" void kernel_launch(void* const* d_in, const int* in_sizes, int n_in,
                              void* d_out, int out_size)
{
    const float* x   = (const float*)d_in[0];
    const float* h0  = (const float*)d_in[1];
    const float* Wxw = (const float*)d_in[2];
    const float* Wxb = (const float*)d_in[3];
    const float* Whw = (const float*)d_in[4];
    const float* Whb = (const float*)d_in[5];
    float* out = (float*)d_out;

    cudaFuncSetAttribute(rnn_fused_kernel,
                         cudaFuncAttributeMaxDynamicSharedMemorySize, SMEM_BYTES);
    rnn_fused_kernel<<<SCAN_BLOCKS, SCAN_THREADS, SMEM_BYTES>>>(
        x, h0, Wxw, Wxb, Whw, Whb, out);
}

// round 14
// speedup vs baseline: 1.2473x; 1.2473x over previous
#include <cuda_runtime.h>
#include <cuda_bf16.h>
#include <stdint.h>
#include <math.h>

#define L_STEPS 512
#define BATCH   128
#define HID     512
#define DIN     512

// ---------------- device scratch ----------------
__device__ __nv_bfloat16 g_h_hi[2][BATCH * HID];
__device__ __nv_bfloat16 g_h_lo[2][BATCH * HID];
__device__ __nv_bfloat16 g_wx_hi[DIN * HID];
__device__ __nv_bfloat16 g_wx_lo[DIN * HID];
__device__ unsigned g_bar_arrive = 0;
__device__ volatile unsigned g_bar_gen = 0;
__device__ unsigned g_garr[8 * 32];
__device__ unsigned g_ggen[8 * 32];

#define SCAN_BLOCKS  64
#define SCAN_THREADS 256
#define GROUP_CTAS   8

// scan smem: Whi[64][520]bf16, Wlo, hhi[16][520]bf16, hlo
#define W_STRIDE 520
#define H_STRIDE 520
#define WS_B (64 * W_STRIDE * 2)      // 66560
#define HS_B (16 * H_STRIDE * 2)      // 16640
#define OFF_WHI  0
#define OFF_WLO  (WS_B)
#define OFF_HHI  (2 * WS_B)
#define OFF_HLO  (2 * WS_B + HS_B)
#define SMEM_BYTES (2 * WS_B + 2 * HS_B)   // 166400

// xproj smem: 4 tiles of [128][72] bf16
#define XP_STRIDE 72
#define XP_TILE_BYTES (128 * XP_STRIDE * 2)
#define XP_AHI 0
#define XP_ALO (XP_TILE_BYTES)
#define XP_BHI (2 * XP_TILE_BYTES)
#define XP_BLO (3 * XP_TILE_BYTES)
#define XP_SMEM (4 * XP_TILE_BYTES)

// ---------------- barriers ----------------
__device__ __forceinline__ void full_grid_barrier() {
    __threadfence();
    __syncthreads();
    if (threadIdx.x == 0) {
        unsigned gen = g_bar_gen;
        if (atomicAdd(&g_bar_arrive, 1u) == SCAN_BLOCKS - 1) {
            g_bar_arrive = 0;
            __threadfence();
            g_bar_gen = gen + 1;
        } else {
            while (g_bar_gen == gen) { __nanosleep(32); }
        }
    }
    __syncthreads();
}

// acq_rel group barrier (R6 semantics), 8 arrivals
__device__ __forceinline__ void group_barrier(int grp) {
    __syncthreads();
    if (threadIdx.x == 0) {
        unsigned* arr = &g_garr[grp * 32];
        unsigned* gen = &g_ggen[grp * 32];
        unsigned g;
        asm volatile("ld.relaxed.gpu.u32 %0, [%1];" : "=r"(g) : "l"(gen));
        unsigned old;
        asm volatile("atom.add.acq_rel.gpu.u32 %0, [%1], 1;" : "=r"(old) : "l"(arr));
        if (old == GROUP_CTAS - 1) {
            asm volatile("st.relaxed.gpu.u32 [%0], 0;" :: "l"(arr));
            unsigned ng = g + 1;
            asm volatile("st.release.gpu.u32 [%0], %1;" :: "l"(gen), "r"(ng));
        } else {
            unsigned cur;
            do {
                __nanosleep(20);
                asm volatile("ld.acquire.gpu.u32 %0, [%1];" : "=r"(cur) : "l"(gen));
            } while (cur == g);
        }
    }
    __syncthreads();
}

#define NB_ARRIVE(id) asm volatile("bar.arrive %0, 256;" :: "r"(id) : "memory")
#define NB_SYNC(id)   asm volatile("bar.sync %0, 256;"   :: "r"(id) : "memory")

// ---------------- mma / ldmatrix helpers ----------------
__device__ __forceinline__ void mma_bf16(float* c,
                                         uint32_t a0, uint32_t a1, uint32_t a2, uint32_t a3,
                                         uint32_t b0, uint32_t b1) {
    asm volatile(
        "mma.sync.aligned.m16n8k16.row.col.f32.bf16.bf16.f32 "
        "{%0,%1,%2,%3}, {%4,%5,%6,%7}, {%8,%9}, {%0,%1,%2,%3};"
        : "+f"(c[0]), "+f"(c[1]), "+f"(c[2]), "+f"(c[3])
        : "r"(a0), "r"(a1), "r"(a2), "r"(a3), "r"(b0), "r"(b1));
}
__device__ __forceinline__ void ldsm_x4(uint32_t r[4], uint32_t addr) {
    asm volatile("ldmatrix.sync.aligned.m8n8.x4.shared.b16 {%0,%1,%2,%3}, [%4];"
                 : "=r"(r[0]), "=r"(r[1]), "=r"(r[2]), "=r"(r[3]) : "r"(addr));
}
__device__ __forceinline__ void split_bf16(float v, __nv_bfloat16& hi, __nv_bfloat16& lo) {
    hi = __float2bfloat16(v);
    lo = __float2bfloat16(v - __bfloat162float(hi));
}
__device__ __forceinline__ float fast_tanh(float x) {
    float e = __expf(2.0f * x);
    return 1.0f - 2.0f / (e + 1.0f);
}

// ---------------- Phase 0: pre-split Wx into bf16 hi/lo -----------------------
__global__ void __launch_bounds__(512) wx_split_kernel(const float* __restrict__ Wx) {
    int idx = blockIdx.x * 512 + threadIdx.x;     // 65536 f4 total
    float4 v = __ldg((const float4*)Wx + idx);
    __nv_bfloat16 h0, l0, h1, l1, h2, l2, h3, l3;
    split_bf16(v.x, h0, l0); split_bf16(v.y, h1, l1);
    split_bf16(v.z, h2, l2); split_bf16(v.w, h3, l3);
    __nv_bfloat162* dH = (__nv_bfloat162*)g_wx_hi + idx * 2;
    __nv_bfloat162* dL = (__nv_bfloat162*)g_wx_lo + idx * 2;
    dH[0] = __nv_bfloat162(h0, h1); dH[1] = __nv_bfloat162(h2, h3);
    dL[0] = __nv_bfloat162(l0, l1); dL[1] = __nv_bfloat162(l2, l3);
}

// ---------------- Phase 1: xproj via bf16-split MMA (R12, unchanged) ----------
__global__ void __launch_bounds__(256, 1) xproj_mma_kernel(
    const float* __restrict__ x,
    const float* __restrict__ bx, const float* __restrict__ bh,
    float* __restrict__ out)
{
    extern __shared__ char sm[];
    __nv_bfloat16* a_hi = (__nv_bfloat16*)(sm + XP_AHI);
    __nv_bfloat16* a_lo = (__nv_bfloat16*)(sm + XP_ALO);
    __nv_bfloat16* b_hi = (__nv_bfloat16*)(sm + XP_BHI);
    __nv_bfloat16* b_lo = (__nv_bfloat16*)(sm + XP_BLO);

    const int tid  = threadIdx.x;
    const int lane = tid & 31;
    const int w    = tid >> 5;
    const int wm   = w & 3;
    const int wn   = w >> 2;
    const int m0   = blockIdx.y << 7;
    const int n0   = blockIdx.x << 7;

    const uint32_t aHiU = (uint32_t)__cvta_generic_to_shared(a_hi);
    const uint32_t aLoU = (uint32_t)__cvta_generic_to_shared(a_lo);
    const uint32_t bHiU = (uint32_t)__cvta_generic_to_shared(b_hi);
    const uint32_t bLoU = (uint32_t)__cvta_generic_to_shared(b_lo);

    const int arow   = (lane & 7) + ((lane >> 3) & 1) * 8;
    const int akoff  = (lane >> 4) * 16;
    const int bn     = ((lane >> 4) << 3) + (lane & 7);
    const int bkoff  = ((lane >> 3) & 1) * 16;

    uint32_t aHiB[2], aLoB[2];
    #pragma unroll
    for (int mi = 0; mi < 2; ++mi) {
        int r = (wm << 5) + (mi << 4) + arow;
        aHiB[mi] = aHiU + r * (XP_STRIDE * 2) + akoff;
        aLoB[mi] = aLoU + r * (XP_STRIDE * 2) + akoff;
    }

    float acc[2][8][4];
    #pragma unroll
    for (int mi = 0; mi < 2; ++mi)
        #pragma unroll
        for (int nf = 0; nf < 8; ++nf)
            #pragma unroll
            for (int r = 0; r < 4; ++r) acc[mi][nf][r] = 0.f;

    const int ldRow = tid >> 4;
    const int ldC4  = tid & 15;

    float4 avc[8];
    #pragma unroll
    for (int t = 0; t < 8; ++t) {
        const int row = ldRow + (t << 4);
        avc[t] = __ldg((const float4*)(x + (size_t)(m0 + row) * DIN) + ldC4);
    }

    for (int kc = 0; kc < DIN; kc += 64) {
        __syncthreads();
        float4 bhv[4], blv[4];
        #pragma unroll
        for (int n = 0; n < 4; ++n) {
            const int i = tid + (n << 8);
            const int brow = i >> 3, bc8 = i & 7;
            const int src = (n0 + brow) * 64 + (kc >> 3) + bc8;
            bhv[n] = __ldg((const float4*)g_wx_hi + src);
            blv[n] = __ldg((const float4*)g_wx_lo + src);
        }
        #pragma unroll
        for (int t = 0; t < 8; ++t) {
            const int row = ldRow + (t << 4);
            __nv_bfloat16 h0, l0, h1, l1, h2, l2, h3, l3;
            split_bf16(avc[t].x, h0, l0); split_bf16(avc[t].y, h1, l1);
            split_bf16(avc[t].z, h2, l2); split_bf16(avc[t].w, h3, l3);
            __nv_bfloat162* pH = (__nv_bfloat162*)(a_hi + row * XP_STRIDE + (ldC4 << 2));
            __nv_bfloat162* pL = (__nv_bfloat162*)(a_lo + row * XP_STRIDE + (ldC4 << 2));
            pH[0] = __nv_bfloat162(h0, h1); pH[1] = __nv_bfloat162(h2, h3);
            pL[0] = __nv_bfloat162(l0, l1); pL[1] = __nv_bfloat162(l2, l3);
        }
        #pragma unroll
        for (int n = 0; n < 4; ++n) {
            const int i = tid + (n << 8);
            const int brow = i >> 3, bc8 = i & 7;
            ((float4*)b_hi)[brow * 9 + bc8] = bhv[n];
            ((float4*)b_lo)[brow * 9 + bc8] = blv[n];
        }
        __syncthreads();

        if (kc + 64 < DIN) {
            #pragma unroll
            for (int t = 0; t < 8; ++t) {
                const int row = ldRow + (t << 4);
                avc[t] = __ldg((const float4*)(x + (size_t)(m0 + row) * DIN + kc + 64) + ldC4);
            }
        }

        #pragma unroll
        for (int k16 = 0; k16 < 4; ++k16) {
            const uint32_t ko = k16 * 32;
            uint32_t ah[2][4], al[2][4];
            ldsm_x4(ah[0], aHiB[0] + ko);
            ldsm_x4(ah[1], aHiB[1] + ko);
            ldsm_x4(al[0], aLoB[0] + ko);
            ldsm_x4(al[1], aLoB[1] + ko);
            #pragma unroll
            for (int np = 0; np < 4; ++np) {
                const uint32_t bOff =
                    ((wn << 6) + (np << 4) + bn) * (XP_STRIDE * 2) + bkoff + ko;
                uint32_t bh4[4], bl4[4];
                ldsm_x4(bh4, bHiU + bOff);
                ldsm_x4(bl4, bLoU + bOff);
                #pragma unroll
                for (int mi = 0; mi < 2; ++mi) {
                    #pragma unroll
                    for (int nf = 0; nf < 2; ++nf) {
                        float* c = acc[mi][(np << 1) + nf];
                        mma_bf16(c, ah[mi][0], ah[mi][1], ah[mi][2], ah[mi][3],
                                 bh4[2 * nf], bh4[2 * nf + 1]);
                        mma_bf16(c, ah[mi][0], ah[mi][1], ah[mi][2], ah[mi][3],
                                 bl4[2 * nf], bl4[2 * nf + 1]);
                        mma_bf16(c, al[mi][0], al[mi][1], al[mi][2], al[mi][3],
                                 bh4[2 * nf], bh4[2 * nf + 1]);
                    }
                }
            }
        }
    }

    const int er = lane >> 2;
    const int ec = (lane & 3) << 1;
    float bb[8][2];
    #pragma unroll
    for (int nf = 0; nf < 8; ++nf) {
        int gn = n0 + (wn << 6) + (nf << 3) + ec;
        bb[nf][0] = __ldg(bx + gn) + __ldg(bh + gn);
        bb[nf][1] = __ldg(bx + gn + 1) + __ldg(bh + gn + 1);
    }
    #pragma unroll
    for (int mi = 0; mi < 2; ++mi) {
        const int gm = m0 + (wm << 5) + (mi << 4) + er;
        #pragma unroll
        for (int nf = 0; nf < 8; ++nf) {
            const int gn = n0 + (wn << 6) + (nf << 3) + ec;
            float* c = acc[mi][nf];
            *(float2*)(out + (size_t)gm * HID + gn) =
                make_float2(c[0] + bb[nf][0], c[1] + bb[nf][1]);
            *(float2*)(out + (size_t)(gm + 8) * HID + gn) =
                make_float2(c[2] + bb[nf][0], c[3] + bb[nf][1]);
        }
    }
}

// ---------------- Phase 2: persistent scan ------------------------------------
// 64 CTAs: bt = blockIdx.x>>3 (16 batch rows), ht = blockIdx.x&7 (64 cols).
// R6 internals: 4 MMA warps (each 16 cols = 2 col-groups), 4 staging warps,
// producer-side bf16 split, 8-arrival acq_rel barrier, chunked h staging.
__global__ void __launch_bounds__(SCAN_THREADS, 1) rnn_scan_kernel(
    const float* __restrict__ h0, const float* __restrict__ Wh,
    float* __restrict__ out)
{
    extern __shared__ char sm[];
    __nv_bfloat16* ws_hi = (__nv_bfloat16*)(sm + OFF_WHI);
    __nv_bfloat16* ws_lo = (__nv_bfloat16*)(sm + OFF_WLO);
    __nv_bfloat16* hs_hi = (__nv_bfloat16*)(sm + OFF_HHI);
    __nv_bfloat16* hs_lo = (__nv_bfloat16*)(sm + OFF_HLO);

    const int tid  = threadIdx.x;
    const int lane = tid & 31;
    const int w    = tid >> 5;
    const int bt = blockIdx.x >> 3;
    const int ht = blockIdx.x & 7;
    const int b0 = bt << 4;        // 16 batch rows
    const int j0 = ht << 6;        // 64 output cols

    // init: split h0 into bf16 hi/lo (16384 f4 total = 1 per thread)
    {
        int idx = blockIdx.x * SCAN_THREADS + tid;
        float4 v = __ldg((const float4*)h0 + idx);
        __nv_bfloat16 h0b, l0b, h1b, l1b, h2b, l2b, h3b, l3b;
        split_bf16(v.x, h0b, l0b); split_bf16(v.y, h1b, l1b);
        split_bf16(v.z, h2b, l2b); split_bf16(v.w, h3b, l3b);
        __nv_bfloat162* dH = (__nv_bfloat162*)(g_h_hi[0]) + idx * 2;
        __nv_bfloat162* dL = (__nv_bfloat162*)(g_h_lo[0]) + idx * 2;
        dH[0] = __nv_bfloat162(h0b, h1b); dH[1] = __nv_bfloat162(h2b, h3b);
        dL[0] = __nv_bfloat162(l0b, l1b); dL[1] = __nv_bfloat162(l2b, l3b);
    }
    // init: split W slice rows j0..j0+63 into smem [n][k]
    for (int i = tid; i < 64 * HID; i += SCAN_THREADS) {
        int n = i >> 9, k = i & 511;
        float v = __ldg(Wh + (size_t)(j0 + n) * HID + k);
        __nv_bfloat16 hi, lo;
        split_bf16(v, hi, lo);
        ws_hi[n * W_STRIDE + k] = hi;
        ws_lo[n * W_STRIDE + k] = lo;
    }
    full_grid_barrier();

    uint32_t hs_hi_u = (uint32_t)__cvta_generic_to_shared(hs_hi);
    uint32_t hs_lo_u = (uint32_t)__cvta_generic_to_shared(hs_lo);
    uint32_t ws_hi_u = (uint32_t)__cvta_generic_to_shared(ws_hi);
    uint32_t ws_lo_u = (uint32_t)__cvta_generic_to_shared(ws_lo);

    // A fragment mapping (warps 0-3)
    const int wj    = w & 3;
    const int arow  = (lane & 7) + ((lane >> 3) & 1) * 8;
    const int akoff = (lane >> 4) * 16;
    const uint32_t aHiBase = hs_hi_u + arow * (H_STRIDE * 2) + akoff;
    const uint32_t aLoBase = hs_lo_u + arow * (H_STRIDE * 2) + akoff;
    // B via ldsm_x4 covering k32 for 8 cols; warp wj owns cols j0+16*wj .. +15
    // col-group g in {0,1}: rows 16*wj + 8*g + (lane&7), chunk = ((lane>>3)&3)*16
    const int bchunk = ((lane >> 3) & 3) * 16;
    uint32_t bHiB[2], bLoB[2];
    #pragma unroll
    for (int g = 0; g < 2; ++g) {
        int r = 16 * wj + 8 * g + (lane & 7);
        bHiB[g] = ws_hi_u + r * (W_STRIDE * 2) + bchunk;
        bLoB[g] = ws_lo_u + r * (W_STRIDE * 2) + bchunk;
    }

    // epilogue mapping: 2 col-groups, 2 row-halves each
    const int er = lane >> 2;
    const int ec = 2 * (lane & 3);
    size_t o1[2], o2[2];
    #pragma unroll
    for (int g = 0; g < 2; ++g) {
        int jcol = j0 + 16 * wj + 8 * g + ec;
        o1[g] = (size_t)(b0 + er) * HID + jcol;
        o2[g] = (size_t)(b0 + er + 8) * HID + jcol;
    }

    int p = 0;

    for (int t = 0; t < L_STEPS; ++t) {
        float* gout = out + (size_t)t * (BATCH * HID);
        float2 xp1[2], xp2[2];
        if (w < 4) {
            #pragma unroll
            for (int g = 0; g < 2; ++g) {
                xp1[g] = *(const float2*)(gout + o1[g]);
                xp2[g] = *(const float2*)(gout + o2[g]);
            }
        }

        const float4* srcH = (const float4*)(g_h_hi[p] + b0 * HID);
        const float4* srcL = (const float4*)(g_h_lo[p] + b0 * HID);
        float4* dH = (float4*)hs_hi;
        float4* dL = (float4*)hs_lo;

        // stage chunk0 (bf16 cols 0..255): all warps
        #pragma unroll
        for (int n = 0; n < 2; ++n) {
            int i = tid + (n << 8);
            int row = i >> 5, c4 = i & 31;
            dH[row * 65 + c4] = __ldcg(srcH + row * 64 + c4);
            dL[row * 65 + c4] = __ldcg(srcL + row * 64 + c4);
        }
        __syncthreads();

        if (w < 4) {
            float chh[2][4] = {}, chl[2][4] = {}, clh[2][4] = {};

            // chunk0: k32 iters 0..7 (overlaps w4-7 staging chunk1)
            #pragma unroll 4
            for (int ki2 = 0; ki2 < 8; ++ki2) {
                const uint32_t koff = ki2 * 64;
                uint32_t ah0[4], al0[4], ah1[4], al1[4];
                ldsm_x4(ah0, aHiBase + koff);
                ldsm_x4(al0, aLoBase + koff);
                ldsm_x4(ah1, aHiBase + koff + 32);
                ldsm_x4(al1, aLoBase + koff + 32);
                #pragma unroll
                for (int g = 0; g < 2; ++g) {
                    uint32_t bh4[4], bl4[4];
                    ldsm_x4(bh4, bHiB[g] + koff);
                    ldsm_x4(bl4, bLoB[g] + koff);
                    mma_bf16(chh[g], ah0[0], ah0[1], ah0[2], ah0[3], bh4[0], bh4[1]);
                    mma_bf16(chl[g], ah0[0], ah0[1], ah0[2], ah0[3], bl4[0], bl4[1]);
                    mma_bf16(clh[g], al0[0], al0[1], al0[2], al0[3], bh4[0], bh4[1]);
                    mma_bf16(chh[g], ah1[0], ah1[1], ah1[2], ah1[3], bh4[2], bh4[3]);
                    mma_bf16(chl[g], ah1[0], ah1[1], ah1[2], ah1[3], bl4[2], bl4[3]);
                    mma_bf16(clh[g], al1[0], al1[1], al1[2], al1[3], bh4[2], bh4[3]);
                }
            }
            NB_SYNC(1);   // chunk1 staged
            #pragma unroll 4
            for (int ki2 = 8; ki2 < 16; ++ki2) {
                const uint32_t koff = ki2 * 64;
                uint32_t ah0[4], al0[4], ah1[4], al1[4];
                ldsm_x4(ah0, aHiBase + koff);
                ldsm_x4(al0, aLoBase + koff);
                ldsm_x4(ah1, aHiBase + koff + 32);
                ldsm_x4(al1, aLoBase + koff + 32);
                #pragma unroll
                for (int g = 0; g < 2; ++g) {
                    uint32_t bh4[4], bl4[4];
                    ldsm_x4(bh4, bHiB[g] + koff);
                    ldsm_x4(bl4, bLoB[g] + koff);
                    mma_bf16(chh[g], ah0[0], ah0[1], ah0[2], ah0[3], bh4[0], bh4[1]);
                    mma_bf16(chl[g], ah0[0], ah0[1], ah0[2], ah0[3], bl4[0], bl4[1]);
                    mma_bf16(clh[g], al0[0], al0[1], al0[2], al0[3], bh4[0], bh4[1]);
                    mma_bf16(chh[g], ah1[0], ah1[1], ah1[2], ah1[3], bh4[2], bh4[3]);
                    mma_bf16(chl[g], ah1[0], ah1[1], ah1[2], ah1[3], bl4[2], bl4[3]);
                    mma_bf16(clh[g], al1[0], al1[1], al1[2], al1[3], bh4[2], bh4[3]);
                }
            }

            __nv_bfloat16* ghh = g_h_hi[p ^ 1];
            __nv_bfloat16* ghl = g_h_lo[p ^ 1];
            float hn[2][4];
            #pragma unroll
            for (int g = 0; g < 2; ++g) {
                hn[g][0] = fast_tanh(chh[g][0] + chl[g][0] + clh[g][0] + xp1[g].x);
                hn[g][1] = fast_tanh(chh[g][1] + chl[g][1] + clh[g][1] + xp1[g].y);
                hn[g][2] = fast_tanh(chh[g][2] + chl[g][2] + clh[g][2] + xp2[g].x);
                hn[g][3] = fast_tanh(chh[g][3] + chl[g][3] + clh[g][3] + xp2[g].y);

                __nv_bfloat16 h0b, l0b, h1b, l1b, h2b, l2b, h3b, l3b;
                split_bf16(hn[g][0], h0b, l0b);
                split_bf16(hn[g][1], h1b, l1b);
                split_bf16(hn[g][2], h2b, l2b);
                split_bf16(hn[g][3], h3b, l3b);

                // publish next-step state FIRST (inter-CTA critical path)
                *(__nv_bfloat162*)(ghh + o1[g]) = __nv_bfloat162(h0b, h1b);
                *(__nv_bfloat162*)(ghh + o2[g]) = __nv_bfloat162(h2b, h3b);
                *(__nv_bfloat162*)(ghl + o1[g]) = __nv_bfloat162(l0b, l1b);
                *(__nv_bfloat162*)(ghl + o2[g]) = __nv_bfloat162(l2b, l3b);
            }

            // hAll fp32 stores (off the critical path)
            #pragma unroll
            for (int g = 0; g < 2; ++g) {
                *(float2*)(gout + o1[g]) = make_float2(hn[g][0], hn[g][1]);
                *(float2*)(gout + o2[g]) = make_float2(hn[g][2], hn[g][3]);
            }

            if (t == L_STEPS - 1) {
                float* hlast = out + (size_t)L_STEPS * BATCH * HID;
                #pragma unroll
                for (int g = 0; g < 2; ++g) {
                    *(float2*)(hlast + o1[g]) = make_float2(hn[g][0], hn[g][1]);
                    *(float2*)(hlast + o2[g]) = make_float2(hn[g][2], hn[g][3]);
                }
            }
        } else {
            // warps 4-7: stage chunk1 (bf16 cols 256..511)
            const int local = tid - 128;
            #pragma unroll
            for (int n = 0; n < 4; ++n) {
                int i = local + (n << 7);
                int row = i >> 5, c4 = 32 + (i & 31);
                dH[row * 65 + c4] = __ldcg(srcH + row * 64 + c4);
                dL[row * 65 + c4] = __ldcg(srcL + row * 64 + c4);
            }
            NB_ARRIVE(1);
        }

        if (t != L_STEPS - 1) group_barrier(bt);
        p ^= 1;
    }
}

// ---------------- launch -------------------------------------------------------
extern "C" void kernel_launch(void* const* d_in, const int* in_sizes, int n_in,
                              void* d_out, int out_size)
{
    const float* x   = (const float*)d_in[0];
    const float* h0  = (const float*)d_in[1];
    const float* Wxw = (const float*)d_in[2];
    const float* Wxb = (const float*)d_in[3];
    const float* Whw = (const float*)d_in[4];
    const float* Whb = (const float*)d_in[5];
    float* out = (float*)d_out;

    wx_split_kernel<<<128, 512>>>(Wxw);

    cudaFuncSetAttribute(xproj_mma_kernel,
                         cudaFuncAttributeMaxDynamicSharedMemorySize, XP_SMEM);
    dim3 g1(HID / 128, (L_STEPS * BATCH) / 128);
    xproj_mma_kernel<<<g1, 256, XP_SMEM>>>(x, Wxb, Whb, out);

    cudaFuncSetAttribute(rnn_scan_kernel,
                         cudaFuncAttributeMaxDynamicSharedMemorySize, SMEM_BYTES);
    rnn_scan_kernel<<<SCAN_BLOCKS, SCAN_THREADS, SMEM_BYTES>>>(h0, Whw, out);
}

// round 15
// speedup vs baseline: 1.3142x; 1.0536x over previous
#include <cuda_runtime.h>
#include <cuda_bf16.h>
#include <stdint.h>
#include <math.h>

#define L_STEPS 512
#define BATCH   128
#define HID     512
#define DIN     512

// ---------------- device scratch ----------------
__device__ __nv_bfloat16 g_h_hi[2][BATCH * HID];
__device__ __nv_bfloat16 g_h_lo[2][BATCH * HID];
__device__ __nv_bfloat16 g_x_hi[(size_t)L_STEPS * BATCH * HID];   // 64MB
__device__ __nv_bfloat16 g_x_lo[(size_t)L_STEPS * BATCH * HID];   // 64MB
__device__ unsigned g_bar_arrive = 0;
__device__ volatile unsigned g_bar_gen = 0;
__device__ unsigned g_garr[8 * 32];
__device__ unsigned g_ggen[8 * 32];

#define SCAN_BLOCKS  128
#define SCAN_THREADS 256

// smem layout (row stride 520 bf16 = 1040 B everywhere)
#define W_STRIDE 520
#define H_STRIDE 520
#define WS_B (32 * W_STRIDE * 2)     // 33280
#define HS_B (16 * H_STRIDE * 2)     // 16640
#define OFF_WHI  0                   // Wh hi  [32][520]
#define OFF_WLO  (WS_B)
#define OFF_XWHI (2 * WS_B)          // Wx hi  [32][520]
#define OFF_XWLO (3 * WS_B)
#define OFF_HHI  (4 * WS_B)          // h hi   [16][520]
#define OFF_HLO  (4 * WS_B + HS_B)
#define OFF_XHI  (4 * WS_B + 2 * HS_B)   // x hi [16][520]
#define OFF_XLO  (4 * WS_B + 3 * HS_B)
#define OFF_XP   (4 * WS_B + 4 * HS_B)   // xp ring [2][16][32] f32
#define SMEM_BYTES (4 * WS_B + 4 * HS_B + 4096)   // 203776

// ---------------- barriers ----------------
__device__ __forceinline__ void full_grid_barrier() {
    __threadfence();
    __syncthreads();
    if (threadIdx.x == 0) {
        unsigned gen = g_bar_gen;
        if (atomicAdd(&g_bar_arrive, 1u) == SCAN_BLOCKS - 1) {
            g_bar_arrive = 0;
            __threadfence();
            g_bar_gen = gen + 1;
        } else {
            while (g_bar_gen == gen) { __nanosleep(32); }
        }
    }
    __syncthreads();
}

// acq_rel group barrier: 16 CTAs of the same bt group (R6 — proven best)
__device__ __forceinline__ void group_barrier(int grp) {
    __syncthreads();
    if (threadIdx.x == 0) {
        unsigned* arr = &g_garr[grp * 32];
        unsigned* gen = &g_ggen[grp * 32];
        unsigned g;
        asm volatile("ld.relaxed.gpu.u32 %0, [%1];" : "=r"(g) : "l"(gen));
        unsigned old;
        asm volatile("atom.add.acq_rel.gpu.u32 %0, [%1], 1;" : "=r"(old) : "l"(arr));
        if (old == 15) {
            asm volatile("st.relaxed.gpu.u32 [%0], 0;" :: "l"(arr));
            unsigned ng = g + 1;
            asm volatile("st.release.gpu.u32 [%0], %1;" :: "l"(gen), "r"(ng));
        } else {
            unsigned cur;
            do {
                __nanosleep(20);
                asm volatile("ld.acquire.gpu.u32 %0, [%1];" : "=r"(cur) : "l"(gen));
            } while (cur == g);
        }
    }
    __syncthreads();
}

#define NB_ARRIVE(id) asm volatile("bar.arrive %0, 256;" :: "r"(id) : "memory")
#define NB_SYNC(id)   asm volatile("bar.sync %0, 256;"   :: "r"(id) : "memory")
#define NB_SYNC_P(id) asm volatile("bar.sync %0, 128;"   :: "r"(id) : "memory")

// ---------------- mma / ldmatrix / cp.async helpers ----------------
__device__ __forceinline__ void mma_bf16(float* c,
                                         uint32_t a0, uint32_t a1, uint32_t a2, uint32_t a3,
                                         uint32_t b0, uint32_t b1) {
    asm volatile(
        "mma.sync.aligned.m16n8k16.row.col.f32.bf16.bf16.f32 "
        "{%0,%1,%2,%3}, {%4,%5,%6,%7}, {%8,%9}, {%0,%1,%2,%3};"
        : "+f"(c[0]), "+f"(c[1]), "+f"(c[2]), "+f"(c[3])
        : "r"(a0), "r"(a1), "r"(a2), "r"(a3), "r"(b0), "r"(b1));
}
__device__ __forceinline__ void ldsm_x4(uint32_t r[4], uint32_t addr) {
    asm volatile("ldmatrix.sync.aligned.m8n8.x4.shared.b16 {%0,%1,%2,%3}, [%4];"
                 : "=r"(r[0]), "=r"(r[1]), "=r"(r[2]), "=r"(r[3]) : "r"(addr));
}
__device__ __forceinline__ void ldsm_x2(uint32_t r[2], uint32_t addr) {
    asm volatile("ldmatrix.sync.aligned.m8n8.x2.shared.b16 {%0,%1}, [%2];"
                 : "=r"(r[0]), "=r"(r[1]) : "r"(addr));
}
__device__ __forceinline__ void cp_async16(uint32_t saddr, const void* gptr) {
    asm volatile("cp.async.ca.shared.global [%0], [%1], 16;"
                 :: "r"(saddr), "l"(gptr) : "memory");
}
#define CP_COMMIT() asm volatile("cp.async.commit_group;" ::: "memory")
#define CP_WAIT0()  asm volatile("cp.async.wait_group 0;" ::: "memory")

__device__ __forceinline__ void split_bf16(float v, __nv_bfloat16& hi, __nv_bfloat16& lo) {
    hi = __float2bfloat16(v);
    lo = __float2bfloat16(v - __bfloat162float(hi));
}
__device__ __forceinline__ float fast_tanh(float x) {
    float e = __expf(2.0f * x);
    return 1.0f - 2.0f / (e + 1.0f);
}

// ---------------- Phase 0: pre-split x into bf16 hi/lo ------------------------
__global__ void __launch_bounds__(1024) x_split_kernel(const float* __restrict__ x) {
    size_t idx = (size_t)blockIdx.x * 1024 + threadIdx.x;   // 8,388,608 f4
    float4 v = __ldg((const float4*)x + idx);
    __nv_bfloat16 h0, l0, h1, l1, h2, l2, h3, l3;
    split_bf16(v.x, h0, l0); split_bf16(v.y, h1, l1);
    split_bf16(v.z, h2, l2); split_bf16(v.w, h3, l3);
    __nv_bfloat162* dH = (__nv_bfloat162*)g_x_hi + idx * 2;
    __nv_bfloat162* dL = (__nv_bfloat162*)g_x_lo + idx * 2;
    dH[0] = __nv_bfloat162(h0, h1); dH[1] = __nv_bfloat162(h2, h3);
    dL[0] = __nv_bfloat162(l0, l1); dL[1] = __nv_bfloat162(l2, l3);
}

// producer xp GEMM: 16x8 output per warp, full K=512, 3-term split, into ring
__device__ __forceinline__ void produce_xp(
    uint32_t xaHi, uint32_t xaLo, uint32_t xbHi, uint32_t xbLo,
    float* ringslot, int er, int pc, float bb0, float bb1)
{
    float chh[4] = {0.f,0.f,0.f,0.f}, chl[4] = {0.f,0.f,0.f,0.f}, clh[4] = {0.f,0.f,0.f,0.f};
    #pragma unroll 4
    for (int ki2 = 0; ki2 < 16; ++ki2) {
        const uint32_t koff = ki2 * 64;
        uint32_t ah0[4], al0[4], ah1[4], al1[4], bh4[4], bl4[4];
        ldsm_x4(ah0, xaHi + koff);
        ldsm_x4(al0, xaLo + koff);
        ldsm_x4(ah1, xaHi + koff + 32);
        ldsm_x4(al1, xaLo + koff + 32);
        ldsm_x4(bh4, xbHi + koff);
        ldsm_x4(bl4, xbLo + koff);
        mma_bf16(chh, ah0[0], ah0[1], ah0[2], ah0[3], bh4[0], bh4[1]);
        mma_bf16(chl, ah0[0], ah0[1], ah0[2], ah0[3], bl4[0], bl4[1]);
        mma_bf16(clh, al0[0], al0[1], al0[2], al0[3], bh4[0], bh4[1]);
        mma_bf16(chh, ah1[0], ah1[1], ah1[2], ah1[3], bh4[2], bh4[3]);
        mma_bf16(chl, ah1[0], ah1[1], ah1[2], ah1[3], bl4[2], bl4[3]);
        mma_bf16(clh, al1[0], al1[1], al1[2], al1[3], bh4[2], bh4[3]);
    }
    *(float2*)(ringslot + er * 32 + pc) =
        make_float2(chh[0] + chl[0] + clh[0] + bb0, chh[1] + chl[1] + clh[1] + bb1);
    *(float2*)(ringslot + (er + 8) * 32 + pc) =
        make_float2(chh[2] + chl[2] + clh[2] + bb0, chh[3] + chl[3] + clh[3] + bb1);
}

// ---------------- fused persistent scan ----------------------------------------
// 128 CTAs, 16-CTA bt groups (R6). Warps 0-3: scan MMA + epilogue (unchanged).
// Warps 4-7: stage h chunk1, then produce xp[t+1] from pre-split x via cp.async
// staging + 3-term MMA into a 2-slot smem ring.
__global__ void __launch_bounds__(SCAN_THREADS, 1) rnn_scan_kernel(
    const float* __restrict__ h0, const float* __restrict__ Wh,
    const float* __restrict__ Wx, const float* __restrict__ bx,
    const float* __restrict__ bh, float* __restrict__ out)
{
    extern __shared__ char sm[];
    __nv_bfloat16* ws_hi = (__nv_bfloat16*)(sm + OFF_WHI);
    __nv_bfloat16* ws_lo = (__nv_bfloat16*)(sm + OFF_WLO);
    __nv_bfloat16* xw_hi = (__nv_bfloat16*)(sm + OFF_XWHI);
    __nv_bfloat16* xw_lo = (__nv_bfloat16*)(sm + OFF_XWLO);
    __nv_bfloat16* hs_hi = (__nv_bfloat16*)(sm + OFF_HHI);
    __nv_bfloat16* hs_lo = (__nv_bfloat16*)(sm + OFF_HLO);
    float*         xpring = (float*)(sm + OFF_XP);

    const int tid  = threadIdx.x;
    const int lane = tid & 31;
    const int w    = tid >> 5;
    const int bt = blockIdx.x >> 4;
    const int ht = blockIdx.x & 15;
    const int b0 = bt << 4;
    const int j0 = ht << 5;

    // init: split h0 into bf16 hi/lo
    {
        int gtid = blockIdx.x * SCAN_THREADS + tid;
        #pragma unroll
        for (int r = 0; r < 2; ++r) {
            int i = gtid + r * (SCAN_BLOCKS * SCAN_THREADS);
            float v = __ldg(h0 + i);
            __nv_bfloat16 hi, lo;
            split_bf16(v, hi, lo);
            g_h_hi[0][i] = hi;
            g_h_lo[0][i] = lo;
        }
    }
    // init: split Wh and Wx slices (rows j0..j0+31) into smem [n][k]
    for (int i = tid; i < 32 * HID; i += SCAN_THREADS) {
        int n = i >> 9, k = i & 511;
        __nv_bfloat16 hi, lo;
        float v = __ldg(Wh + (size_t)(j0 + n) * HID + k);
        split_bf16(v, hi, lo);
        ws_hi[n * W_STRIDE + k] = hi;
        ws_lo[n * W_STRIDE + k] = lo;
        float u = __ldg(Wx + (size_t)(j0 + n) * HID + k);
        split_bf16(u, hi, lo);
        xw_hi[n * W_STRIDE + k] = hi;
        xw_lo[n * W_STRIDE + k] = lo;
    }
    full_grid_barrier();

    uint32_t hs_hi_u = (uint32_t)__cvta_generic_to_shared(hs_hi);
    uint32_t hs_lo_u = (uint32_t)__cvta_generic_to_shared(hs_lo);
    uint32_t ws_hi_u = (uint32_t)__cvta_generic_to_shared(ws_hi);
    uint32_t ws_lo_u = (uint32_t)__cvta_generic_to_shared(ws_lo);
    uint32_t xs_hi_u = (uint32_t)__cvta_generic_to_shared(sm + OFF_XHI);
    uint32_t xs_lo_u = (uint32_t)__cvta_generic_to_shared(sm + OFF_XLO);
    uint32_t xw_hi_u = (uint32_t)__cvta_generic_to_shared(xw_hi);
    uint32_t xw_lo_u = (uint32_t)__cvta_generic_to_shared(xw_lo);

    // A fragment mapping (shared by consumer h-GEMM and producer x-GEMM)
    const int arow  = (lane & 7) + ((lane >> 3) & 1) * 8;
    const int akoff = (lane >> 4) * 16;
    const uint32_t aHiBase  = hs_hi_u + arow * (H_STRIDE * 2) + akoff;
    const uint32_t aLoBase  = hs_lo_u + arow * (H_STRIDE * 2) + akoff;
    const uint32_t xaHiBase = xs_hi_u + arow * (H_STRIDE * 2) + akoff;
    const uint32_t xaLoBase = xs_lo_u + arow * (H_STRIDE * 2) + akoff;
    // consumer B (x2 loads, R6): warp w (0..3) owns cols j0+8w..+7
    const int cbrow  = 8 * (w & 3) + (lane & 7);
    const int bkoff  = ((lane >> 3) & 1) * 16;
    const uint32_t bHiBase = ws_hi_u + cbrow * (W_STRIDE * 2) + bkoff;
    const uint32_t bLoBase = ws_lo_u + cbrow * (W_STRIDE * 2) + bkoff;
    // producer B (x4 loads): warp w-4 owns cols j0+8(w-4)..+7
    const int bchunk = ((lane >> 3) & 3) * 16;
    const uint32_t xbHiBase = xw_hi_u + cbrow * (W_STRIDE * 2) + bchunk;
    const uint32_t xbLoBase = xw_lo_u + cbrow * (W_STRIDE * 2) + bchunk;

    const int er = lane >> 2;
    const int ec = 2 * (lane & 3);
    const int pc = 8 * (w & 3) + ec;            // ring col for this warp's frags
    const int jcol = j0 + pc;
    const size_t o1 = (size_t)(b0 + er) * HID + jcol;
    const size_t o2 = (size_t)(b0 + er + 8) * HID + jcol;

    const float bb0 = __ldg(bx + jcol) + __ldg(bh + jcol);
    const float bb1 = __ldg(bx + jcol + 1) + __ldg(bh + jcol + 1);
    const int local = tid - 128;

    // ---- prologue: producers build xp[0] into ring slot 0 ----
    if (w >= 4) {
        const char* srcXH = (const char*)(g_x_hi + (size_t)b0 * HID);
        const char* srcXL = (const char*)(g_x_lo + (size_t)b0 * HID);
        #pragma unroll
        for (int n = 0; n < 8; ++n) {
            int i = local + (n << 7);
            int row = i >> 6, c16 = i & 63;
            cp_async16(xs_hi_u + row * 1040 + c16 * 16, srcXH + row * 1024 + c16 * 16);
            cp_async16(xs_lo_u + row * 1040 + c16 * 16, srcXL + row * 1024 + c16 * 16);
        }
        CP_COMMIT();
        CP_WAIT0();
        NB_SYNC_P(3);
        produce_xp(xaHiBase, xaLoBase, xbHiBase, xbLoBase, xpring, er, pc, bb0, bb1);
    }
    __syncthreads();

    int p = 0;
    for (int t = 0; t < L_STEPS; ++t) {
        // producers: kick off cp.async for x[t+1] (consumed later this step)
        if (w >= 4 && t + 1 < L_STEPS) {
            const char* srcXH = (const char*)(g_x_hi + ((size_t)(t + 1) * BATCH + b0) * HID);
            const char* srcXL = (const char*)(g_x_lo + ((size_t)(t + 1) * BATCH + b0) * HID);
            #pragma unroll
            for (int n = 0; n < 8; ++n) {
                int i = local + (n << 7);
                int row = i >> 6, c16 = i & 63;
                cp_async16(xs_hi_u + row * 1040 + c16 * 16, srcXH + row * 1024 + c16 * 16);
                cp_async16(xs_lo_u + row * 1040 + c16 * 16, srcXL + row * 1024 + c16 * 16);
            }
            CP_COMMIT();
        }

        const float4* srcH = (const float4*)(g_h_hi[p] + b0 * HID);
        const float4* srcL = (const float4*)(g_h_lo[p] + b0 * HID);
        float4* dH = (float4*)hs_hi;
        float4* dL = (float4*)hs_lo;

        // stage h chunk0 (bf16 cols 0..255): all warps
        #pragma unroll
        for (int n = 0; n < 2; ++n) {
            int i = tid + (n << 8);
            int row = i >> 5, c4 = i & 31;
            dH[row * 65 + c4] = __ldcg(srcH + row * 64 + c4);
            dL[row * 65 + c4] = __ldcg(srcL + row * 64 + c4);
        }
        __syncthreads();

        float* gout = out + (size_t)t * (BATCH * HID);

        if (w < 4) {
            // xp from ring (written at step t-1 / prologue; ordered by barrier)
            const float* ring = xpring + (t & 1) * 512;
            float2 xp1 = *(const float2*)(ring + er * 32 + pc);
            float2 xp2 = *(const float2*)(ring + (er + 8) * 32 + pc);

            float chh[4] = {0.f,0.f,0.f,0.f}, chl[4] = {0.f,0.f,0.f,0.f}, clh[4] = {0.f,0.f,0.f,0.f};
            #pragma unroll 8
            for (int ki = 0; ki < 16; ++ki) {
                const uint32_t koff = ki * 32;
                uint32_t ah[4], al[4], bh2[2], bl2[2];
                ldsm_x4(ah, aHiBase + koff);
                ldsm_x4(al, aLoBase + koff);
                ldsm_x2(bh2, bHiBase + koff);
                ldsm_x2(bl2, bLoBase + koff);
                mma_bf16(chh, ah[0], ah[1], ah[2], ah[3], bh2[0], bh2[1]);
                mma_bf16(chl, ah[0], ah[1], ah[2], ah[3], bl2[0], bl2[1]);
                mma_bf16(clh, al[0], al[1], al[2], al[3], bh2[0], bh2[1]);
            }
            NB_SYNC(1);   // chunk1 staged by producers
            #pragma unroll 8
            for (int ki = 16; ki < 32; ++ki) {
                const uint32_t koff = ki * 32;
                uint32_t ah[4], al[4], bh2[2], bl2[2];
                ldsm_x4(ah, aHiBase + koff);
                ldsm_x4(al, aLoBase + koff);
                ldsm_x2(bh2, bHiBase + koff);
                ldsm_x2(bl2, bLoBase + koff);
                mma_bf16(chh, ah[0], ah[1], ah[2], ah[3], bh2[0], bh2[1]);
                mma_bf16(chl, ah[0], ah[1], ah[2], ah[3], bl2[0], bl2[1]);
                mma_bf16(clh, al[0], al[1], al[2], al[3], bh2[0], bh2[1]);
            }

            float hn0 = fast_tanh(chh[0] + chl[0] + clh[0] + xp1.x);
            float hn1 = fast_tanh(chh[1] + chl[1] + clh[1] + xp1.y);
            float hn2 = fast_tanh(chh[2] + chl[2] + clh[2] + xp2.x);
            float hn3 = fast_tanh(chh[3] + chl[3] + clh[3] + xp2.y);

            __nv_bfloat16 h0b, l0b, h1b, l1b, h2b, l2b, h3b, l3b;
            split_bf16(hn0, h0b, l0b);
            split_bf16(hn1, h1b, l1b);
            split_bf16(hn2, h2b, l2b);
            split_bf16(hn3, h3b, l3b);

            // publish next-step state FIRST (inter-CTA critical path)
            __nv_bfloat16* ghh = g_h_hi[p ^ 1];
            __nv_bfloat16* ghl = g_h_lo[p ^ 1];
            *(__nv_bfloat162*)(ghh + o1) = __nv_bfloat162(h0b, h1b);
            *(__nv_bfloat162*)(ghh + o2) = __nv_bfloat162(h2b, h3b);
            *(__nv_bfloat162*)(ghl + o1) = __nv_bfloat162(l0b, l1b);
            *(__nv_bfloat162*)(ghl + o2) = __nv_bfloat162(l2b, l3b);

            // hAll fp32 stores
            *(float2*)(gout + o1) = make_float2(hn0, hn1);
            *(float2*)(gout + o2) = make_float2(hn2, hn3);

            if (t == L_STEPS - 1) {
                float* hlast = out + (size_t)L_STEPS * BATCH * HID;
                *(float2*)(hlast + o1) = make_float2(hn0, hn1);
                *(float2*)(hlast + o2) = make_float2(hn2, hn3);
            }
        } else {
            // stage h chunk1 (bf16 cols 256..511)
            #pragma unroll
            for (int n = 0; n < 4; ++n) {
                int i = local + (n << 7);
                int row = i >> 5, c4 = 32 + (i & 31);
                dH[row * 65 + c4] = __ldcg(srcH + row * 64 + c4);
                dL[row * 65 + c4] = __ldcg(srcL + row * 64 + c4);
            }
            NB_ARRIVE(1);

            if (t + 1 < L_STEPS) {
                CP_WAIT0();
                NB_SYNC_P(3);   // all producer warps' x tile in smem
                produce_xp(xaHiBase, xaLoBase, xbHiBase, xbLoBase,
                           xpring + ((t + 1) & 1) * 512, er, pc, bb0, bb1);
            }
        }

        if (t != L_STEPS - 1) group_barrier(bt);
        p ^= 1;
    }
}

// ---------------- launch -------------------------------------------------------
extern "C" void kernel_launch(void* const* d_in, const int* in_sizes, int n_in,
                              void* d_out, int out_size)
{
    const float* x   = (const float*)d_in[0];
    const float* h0  = (const float*)d_in[1];
    const float* Wxw = (const float*)d_in[2];
    const float* Wxb = (const float*)d_in[3];
    const float* Whw = (const float*)d_in[4];
    const float* Whb = (const float*)d_in[5];
    float* out = (float*)d_out;

    // pre-split x into bf16 hi/lo (8,388,608 f4)
    x_split_kernel<<<8192, 1024>>>(x);

    cudaFuncSetAttribute(rnn_scan_kernel,
                         cudaFuncAttributeMaxDynamicSharedMemorySize, SMEM_BYTES);
    rnn_scan_kernel<<<SCAN_BLOCKS, SCAN_THREADS, SMEM_BYTES>>>(
        h0, Whw, Wxw, Wxb, Whb, out);
}